// round 10
// baseline (speedup 1.0000x reference)
#include <cuda_runtime.h>
#include <cuda_fp16.h>
#include <cstdint>

#define N_NODES   50000
#define F_DIM     256
#define N_EDGES   800000
#define PAD_M     50048          // 391 * 128

#define SCAN_B    256
#define SCAN_NB   ((N_NODES + SCAN_B - 1) / SCAN_B)   // 196

// Launch A roles: hist (+rank) | prep_w
#define HIST_B    3125                      // ceil(800000/256)
#define PREPW_B   64
#define F1_BLOCKS (HIST_B + PREPW_B)

// Scratch (__device__ globals; no allocation allowed)
__device__ __half g_yh[(size_t)N_NODES * F_DIM];  // Y = X @ W^T, fp16
__device__ __half g_wh[F_DIM * F_DIM];            // W in fp16
__device__ int    g_cnt[N_NODES];
__device__ int    g_off[N_NODES + 1];
__device__ int    g_rank[N_EDGES];                // edge rank within its row
__device__ unsigned long long g_scan_pkt[SCAN_NB];
__device__ int2   g_cv[N_EDGES];                  // packed (col, val-bits)

// ---------------------------------------------------------------------------
// Fused launch A: hist (stores per-edge rank) | prep_w
// ---------------------------------------------------------------------------
__global__ __launch_bounds__(256)
void k_fused_a(const int*   __restrict__ edge_row,
               const float* __restrict__ W) {
    int bid = blockIdx.x;
    int tid = threadIdx.x;
    if (bid < HIST_B) {
        int e = bid * 256 + tid;
        if (e < N_EDGES) {
            int r = edge_row[e];
            g_rank[e] = atomicAdd(&g_cnt[r], 1);   // rank within row
        }
    } else {
        int i = (bid - HIST_B) * 256 + tid;        // float4 index, 16384 total
        float4 v = reinterpret_cast<const float4*>(W)[i];
        __half2 h0 = __floats2half2_rn(v.x, v.y);
        __half2 h1 = __floats2half2_rn(v.z, v.w);
        reinterpret_cast<__half2*>(g_wh)[2 * i]     = h0;
        reinterpret_cast<__half2*>(g_wh)[2 * i + 1] = h1;
    }
}

// ---------------------------------------------------------------------------
// Single-pass decoupled-lookback scan
// ---------------------------------------------------------------------------
__global__ void k_scan_fused() {
    __shared__ int warp_sums[8];
    __shared__ int s_base;
    const int b    = blockIdx.x;
    const int t    = threadIdx.x;
    const int lane = t & 31;
    const int w    = t >> 5;
    const int i    = b * SCAN_B + t;

    int v = (i < N_NODES) ? g_cnt[i] : 0;

    int inc = v;
#pragma unroll
    for (int d = 1; d < 32; d <<= 1) {
        int tt = __shfl_up_sync(0xffffffffu, inc, d);
        if (lane >= d) inc += tt;
    }
    if (lane == 31) warp_sums[w] = inc;
    __syncthreads();
    if (w == 0) {
        int ws = (lane < 8) ? warp_sums[lane] : 0;
#pragma unroll
        for (int d = 1; d < 8; d <<= 1) {
            int tt = __shfl_up_sync(0xffffffffu, ws, d);
            if (lane >= d) ws += tt;
        }
        if (lane < 8) warp_sums[lane] = ws;
    }
    __syncthreads();
    int excl  = inc - v + ((w > 0) ? warp_sums[w - 1] : 0);
    int total = warp_sums[7];

    if (t == 0) {
        if (b == 0) {
            atomicExch(&g_scan_pkt[0], (2ULL << 62) | (unsigned)total);
            s_base = 0;
        } else {
            atomicExch(&g_scan_pkt[b], (1ULL << 62) | (unsigned)total);
            int run = 0;
            int j = b - 1;
            while (true) {
                unsigned long long p;
                while (((p = atomicAdd(&g_scan_pkt[j], 0ULL)) >> 62) == 0) {}
                run += (int)(p & 0xFFFFFFFFULL);
                if ((p >> 62) == 2ULL) break;
                j--;
            }
            atomicExch(&g_scan_pkt[b], (2ULL << 62) | (unsigned)(run + total));
            s_base = run;
        }
    }
    __syncthreads();
    int base = s_base;
    if (i < N_NODES) g_off[i] = base + excl;
    if (i == N_NODES - 1) g_off[N_NODES] = N_EDGES;
}

// ---------------------------------------------------------------------------
// Scatter: atomic-free, position = off[row] + rank
// ---------------------------------------------------------------------------
__global__ __launch_bounds__(256)
void k_scatter(const int*   __restrict__ edge_row,
               const int*   __restrict__ edge_col,
               const float* __restrict__ edge_val) {
    int e = blockIdx.x * blockDim.x + threadIdx.x;
    if (e < N_EDGES) {
        int r = edge_row[e];
        int p = g_off[r] + g_rank[e];
        g_cv[p] = make_int2(edge_col[e], __float_as_int(edge_val[e]));
    }
}

// ---------------------------------------------------------------------------
// GEMM  Y[m,n] = sum_k X[m,k]*W[n,k]  (fp16 MMA, fp32 acc)
// CTA 128x128, BK=32, 8 warps 4(M) x 2(N), 256 threads.
// Double-buffered smem + register prefetch: one __syncthreads per K-iter,
// LDGs for tile k+1 issue before the MMAs of tile k (latency hidden).
// ---------------------------------------------------------------------------
#define BM 128
#define BN 128
#define BK 32
#define LDS_K 40
#define KTILES (F_DIM / BK)   // 8

__device__ __forceinline__ void mma_f16(float* c, const uint32_t* a, const uint32_t* b) {
    asm volatile(
        "mma.sync.aligned.m16n8k16.row.col.f32.f16.f16.f32 "
        "{%0,%1,%2,%3}, {%4,%5,%6,%7}, {%8,%9}, {%0,%1,%2,%3};"
        : "+f"(c[0]), "+f"(c[1]), "+f"(c[2]), "+f"(c[3])
        : "r"(a[0]), "r"(a[1]), "r"(a[2]), "r"(a[3]), "r"(b[0]), "r"(b[1]));
}

__global__ __launch_bounds__(256)
void gemm_kernel(const float* __restrict__ X) {
    __shared__ __half As[2][BM][LDS_K];   // 2 x 10 KB
    __shared__ __half Ws[2][BN][LDS_K];   // 2 x 10 KB

    const int t    = threadIdx.x;
    const int lane = t & 31;
    const int wid  = t >> 5;
    const int wm   = wid & 3;
    const int wn   = wid >> 2;
    const int g    = lane >> 2;
    const int tid4 = lane & 3;

    const int m0 = blockIdx.x * BM;
    const int n0 = blockIdx.y * BN;

    // ---- loop-invariant staging geometry ----
    // X: 4 float4 loads per thread per tile
    int rowA[4], c4A[4];
    const float* xptr[4];
    bool mokA[4];
#pragma unroll
    for (int i = 0; i < 4; i++) {
        int idx = t + i * 256;
        rowA[i] = idx >> 3;            // 0..127
        c4A[i]  = idx & 7;             // 0..7
        int m   = m0 + rowA[i];
        mokA[i] = (m < N_NODES);
        xptr[i] = X + (size_t)(mokA[i] ? m : 0) * F_DIM + c4A[i] * 4;
    }
    // W: 2 uint4 loads per thread per tile
    int rowW[2], c8W[2];
    const __half* wptr[2];
#pragma unroll
    for (int i = 0; i < 2; i++) {
        int idx = t + i * 256;
        rowW[i] = idx >> 2;            // 0..127
        c8W[i]  = idx & 3;             // 0..3
        wptr[i] = g_wh + (size_t)(n0 + rowW[i]) * F_DIM + c8W[i] * 8;
    }

    float4 xr[4];
    uint4  wr[2];

    // ---- prologue: prefetch tile 0 ----
#pragma unroll
    for (int i = 0; i < 4; i++)
        xr[i] = mokA[i] ? *reinterpret_cast<const float4*>(xptr[i])
                        : make_float4(0.f, 0.f, 0.f, 0.f);
#pragma unroll
    for (int i = 0; i < 2; i++)
        wr[i] = *reinterpret_cast<const uint4*>(wptr[i]);

    float acc[2][8][4];
#pragma unroll
    for (int i = 0; i < 2; i++)
#pragma unroll
        for (int j = 0; j < 8; j++)
#pragma unroll
            for (int k = 0; k < 4; k++) acc[i][j][k] = 0.f;

#pragma unroll
    for (int kt = 0; kt < KTILES; kt++) {
        const int buf = kt & 1;
        // ---- store prefetched regs to smem[buf] ----
#pragma unroll
        for (int i = 0; i < 4; i++) {
            __half2 h0 = __floats2half2_rn(xr[i].x, xr[i].y);
            __half2 h1 = __floats2half2_rn(xr[i].z, xr[i].w);
            uint2 u;
            u.x = *reinterpret_cast<uint32_t*>(&h0);
            u.y = *reinterpret_cast<uint32_t*>(&h1);
            *reinterpret_cast<uint2*>(&As[buf][rowA[i]][c4A[i] * 4]) = u;
        }
#pragma unroll
        for (int i = 0; i < 2; i++)
            *reinterpret_cast<uint4*>(&Ws[buf][rowW[i]][c8W[i] * 8]) = wr[i];
        __syncthreads();

        // ---- prefetch next tile (LDGs issue before MMAs) ----
        if (kt + 1 < KTILES) {
            const int koff = (kt + 1) * BK;
#pragma unroll
            for (int i = 0; i < 4; i++)
                xr[i] = mokA[i] ? *reinterpret_cast<const float4*>(xptr[i] + koff)
                                : make_float4(0.f, 0.f, 0.f, 0.f);
#pragma unroll
            for (int i = 0; i < 2; i++)
                wr[i] = *reinterpret_cast<const uint4*>(wptr[i] + koff);
        }

        // ---- compute from smem[buf] ----
#pragma unroll
        for (int ks = 0; ks < 2; ks++) {
            int kb = ks * 16;
            uint32_t a[2][4];
#pragma unroll
            for (int mi = 0; mi < 2; mi++) {
                int r = wm * 32 + mi * 16;
                a[mi][0] = *reinterpret_cast<const uint32_t*>(&As[buf][r + g    ][kb + 2 * tid4]);
                a[mi][1] = *reinterpret_cast<const uint32_t*>(&As[buf][r + g + 8][kb + 2 * tid4]);
                a[mi][2] = *reinterpret_cast<const uint32_t*>(&As[buf][r + g    ][kb + 2 * tid4 + 8]);
                a[mi][3] = *reinterpret_cast<const uint32_t*>(&As[buf][r + g + 8][kb + 2 * tid4 + 8]);
            }
            uint32_t b[8][2];
#pragma unroll
            for (int ni = 0; ni < 8; ni++) {
                int n = wn * 64 + ni * 8 + g;
                b[ni][0] = *reinterpret_cast<const uint32_t*>(&Ws[buf][n][kb + 2 * tid4]);
                b[ni][1] = *reinterpret_cast<const uint32_t*>(&Ws[buf][n][kb + 2 * tid4 + 8]);
            }
#pragma unroll
            for (int mi = 0; mi < 2; mi++)
#pragma unroll
                for (int ni = 0; ni < 8; ni++)
                    mma_f16(acc[mi][ni], a[mi], b[ni]);
        }
        // no trailing sync: next iteration stores to the other buffer; the
        // sync at the top of iteration kt+1 orders compute(kt) before store(kt+2).
    }

    // store Y as fp16
#pragma unroll
    for (int mi = 0; mi < 2; mi++) {
        int r_base = m0 + wm * 32 + mi * 16;
#pragma unroll
        for (int ni = 0; ni < 8; ni++) {
            int col = n0 + wn * 64 + ni * 8 + 2 * tid4;
            int r0 = r_base + g;
            int r1 = r_base + g + 8;
            if (r0 < N_NODES) {
                __half2 h = __floats2half2_rn(acc[mi][ni][0], acc[mi][ni][1]);
                *reinterpret_cast<__half2*>(g_yh + (size_t)r0 * F_DIM + col) = h;
            }
            if (r1 < N_NODES) {
                __half2 h = __floats2half2_rn(acc[mi][ni][2], acc[mi][ni][3]);
                *reinterpret_cast<__half2*>(g_yh + (size_t)r1 * F_DIM + col) = h;
            }
        }
    }
}

// ---------------------------------------------------------------------------
// Gather: out[r] = sum_e val_e * Y[col_e] + b.  One warp per row.
// Packed f32x2 FMA (sm_103a FFMA2).
// ---------------------------------------------------------------------------
__device__ __forceinline__ void fma8_x2(unsigned long long* acc, uint4 u,
                                        unsigned long long v2) {
    const __half2* h = reinterpret_cast<const __half2*>(&u);
#pragma unroll
    for (int q = 0; q < 4; q++) {
        float2 f = __half22float2(h[q]);
        unsigned long long fu;
        asm("mov.b64 %0, {%1, %2};" : "=l"(fu) : "f"(f.x), "f"(f.y));
        asm("fma.rn.f32x2 %0, %1, %2, %0;" : "+l"(acc[q]) : "l"(fu), "l"(v2));
    }
}

__global__ __launch_bounds__(256, 6)
void k_gather(const float* __restrict__ bias, float* __restrict__ out) {
    int r    = (blockIdx.x * blockDim.x + threadIdx.x) >> 5;
    int lane = threadIdx.x & 31;
    if (r >= N_NODES) return;

    unsigned long long acc[4];
#pragma unroll
    for (int q = 0; q < 4; q++) acc[q] = 0ULL;

    int start = g_off[r];
    int end   = g_off[r + 1];

    for (int base = start; base < end; base += 32) {
        int n = min(32, end - base);
        int   col = 0;
        float val = 0.f;
        if (lane < n) {
            int2 cv = __ldg(&g_cv[base + lane]);
            col = cv.x;
            val = __int_as_float(cv.y);
        }
        int j = 0;
        for (; j + 4 <= n; j += 4) {
            int   c0 = __shfl_sync(0xffffffffu, col, j);
            int   c1 = __shfl_sync(0xffffffffu, col, j + 1);
            int   c2 = __shfl_sync(0xffffffffu, col, j + 2);
            int   c3 = __shfl_sync(0xffffffffu, col, j + 3);
            float v0 = __shfl_sync(0xffffffffu, val, j);
            float v1 = __shfl_sync(0xffffffffu, val, j + 1);
            float v2 = __shfl_sync(0xffffffffu, val, j + 2);
            float v3 = __shfl_sync(0xffffffffu, val, j + 3);
            uint4 u0 = __ldg(reinterpret_cast<const uint4*>(g_yh + (size_t)c0 * F_DIM) + lane);
            uint4 u1 = __ldg(reinterpret_cast<const uint4*>(g_yh + (size_t)c1 * F_DIM) + lane);
            uint4 u2 = __ldg(reinterpret_cast<const uint4*>(g_yh + (size_t)c2 * F_DIM) + lane);
            uint4 u3 = __ldg(reinterpret_cast<const uint4*>(g_yh + (size_t)c3 * F_DIM) + lane);
            unsigned long long p0, p1, p2, p3;
            asm("mov.b64 %0, {%1, %1};" : "=l"(p0) : "f"(v0));
            asm("mov.b64 %0, {%1, %1};" : "=l"(p1) : "f"(v1));
            asm("mov.b64 %0, {%1, %1};" : "=l"(p2) : "f"(v2));
            asm("mov.b64 %0, {%1, %1};" : "=l"(p3) : "f"(v3));
            fma8_x2(acc, u0, p0);
            fma8_x2(acc, u1, p1);
            fma8_x2(acc, u2, p2);
            fma8_x2(acc, u3, p3);
        }
        for (; j < n; j++) {
            int   c = __shfl_sync(0xffffffffu, col, j);
            float v = __shfl_sync(0xffffffffu, val, j);
            uint4 u = __ldg(reinterpret_cast<const uint4*>(g_yh + (size_t)c * F_DIM) + lane);
            unsigned long long p;
            asm("mov.b64 %0, {%1, %1};" : "=l"(p) : "f"(v));
            fma8_x2(acc, u, p);
        }
    }

    float a[8];
#pragma unroll
    for (int q = 0; q < 4; q++) {
        float lo, hi;
        asm("mov.b64 {%0, %1}, %2;" : "=f"(lo), "=f"(hi) : "l"(acc[q]));
        a[2 * q]     = lo;
        a[2 * q + 1] = hi;
    }
    const float4* bp = reinterpret_cast<const float4*>(bias + lane * 8);
    float4 b0 = __ldg(bp);
    float4 b1 = __ldg(bp + 1);
    float4 o0 = make_float4(a[0] + b0.x, a[1] + b0.y, a[2] + b0.z, a[3] + b0.w);
    float4 o1 = make_float4(a[4] + b1.x, a[5] + b1.y, a[6] + b1.z, a[7] + b1.w);
    float4* orow = reinterpret_cast<float4*>(out + (size_t)r * F_DIM + lane * 8);
    orow[0] = o0;
    orow[1] = o1;
}

// ---------------------------------------------------------------------------
// Launch
// ---------------------------------------------------------------------------
extern "C" void kernel_launch(void* const* d_in, const int* in_sizes, int n_in,
                              void* d_out, int out_size) {
    const float* x        = (const float*)d_in[0];
    const int*   edge_row = (const int*)  d_in[1];
    const int*   edge_col = (const int*)  d_in[2];
    const float* edge_val = (const float*)d_in[3];
    const float* W        = (const float*)d_in[4];
    const float* b        = (const float*)d_in[5];
    float*       out      = (float*)d_out;

    void* cnt_ptr = nullptr;
    cudaGetSymbolAddress(&cnt_ptr, g_cnt);
    cudaMemsetAsync(cnt_ptr, 0, N_NODES * sizeof(int));
    void* pkt_ptr = nullptr;
    cudaGetSymbolAddress(&pkt_ptr, g_scan_pkt);
    cudaMemsetAsync(pkt_ptr, 0, SCAN_NB * sizeof(unsigned long long));

    // A: hist (+rank) | prep_w
    k_fused_a<<<F1_BLOCKS, 256>>>(edge_row, W);
    // B: scan
    k_scan_fused<<<SCAN_NB, SCAN_B>>>();
    // C: scatter (atomic-free)
    k_scatter<<<(N_EDGES + 255) / 256, 256>>>(edge_row, edge_col, edge_val);
    // D: GEMM (double-buffered, prefetched)
    dim3 grid(PAD_M / BM, F_DIM / BN);   // 391 x 2
    gemm_kernel<<<grid, 256>>>(x);
    // E: gather
    k_gather<<<(N_NODES * 32 + 255) / 256, 256>>>(b, out);
}

// round 11
// speedup vs baseline: 1.1564x; 1.1564x over previous
#include <cuda_runtime.h>
#include <cuda_fp16.h>
#include <cstdint>

#define N_NODES   50000
#define F_DIM     256
#define N_EDGES   800000
#define PAD_M     50048          // 391 * 128

#define SCAN_B    256
#define SCAN_NB   ((N_NODES + SCAN_B - 1) / SCAN_B)   // 196

// Launch A roles: hist (+rank) | prep_w | prep_x
#define HIST_B    3125                      // ceil(800000/256)
#define PREPW_B   64
#define PREPX_B   6250                      // 50000*256/8/256
#define F1_BLOCKS (HIST_B + PREPW_B + PREPX_B)

// Scratch (__device__ globals; no allocation allowed)
__device__ __half g_yh[(size_t)N_NODES * F_DIM];  // Y = X @ W^T, fp16
__device__ __half g_xh[(size_t)N_NODES * F_DIM];  // X in fp16
__device__ __half g_wh[F_DIM * F_DIM];            // W in fp16
__device__ int    g_cnt[N_NODES];
__device__ int    g_off[N_NODES + 1];
__device__ int    g_rank[N_EDGES];                // edge rank within its row
__device__ unsigned long long g_scan_pkt[SCAN_NB];
__device__ int2   g_cv[N_EDGES];                  // packed (col, val-bits)

// ---------------------------------------------------------------------------
// cp.async helpers
// ---------------------------------------------------------------------------
__device__ __forceinline__ void cp_async16(uint32_t smem_addr, const void* gptr,
                                           int src_size) {
    asm volatile("cp.async.cg.shared.global [%0], [%1], 16, %2;"
                 :: "r"(smem_addr), "l"(gptr), "r"(src_size));
}
__device__ __forceinline__ void cp_commit() {
    asm volatile("cp.async.commit_group;");
}
template <int N>
__device__ __forceinline__ void cp_wait() {
    asm volatile("cp.async.wait_group %0;" :: "n"(N));
}

// ---------------------------------------------------------------------------
// Fused launch A: hist (stores per-edge rank) | prep_w | prep_x
// ---------------------------------------------------------------------------
__global__ __launch_bounds__(256)
void k_fused_a(const int*   __restrict__ edge_row,
               const float* __restrict__ W,
               const float* __restrict__ X) {
    int bid = blockIdx.x;
    int tid = threadIdx.x;
    if (bid < HIST_B) {
        int e = bid * 256 + tid;
        if (e < N_EDGES) {
            int r = edge_row[e];
            g_rank[e] = atomicAdd(&g_cnt[r], 1);   // rank within row
        }
    } else if (bid < HIST_B + PREPW_B) {
        int i = (bid - HIST_B) * 256 + tid;        // float4 index, 16384 total
        float4 v = reinterpret_cast<const float4*>(W)[i];
        __half2 h0 = __floats2half2_rn(v.x, v.y);
        __half2 h1 = __floats2half2_rn(v.z, v.w);
        reinterpret_cast<__half2*>(g_wh)[2 * i]     = h0;
        reinterpret_cast<__half2*>(g_wh)[2 * i + 1] = h1;
    } else {
        int i = (bid - HIST_B - PREPW_B) * 256 + tid;   // 8-half chunk
        const float4* xp = reinterpret_cast<const float4*>(X) + 2 * (size_t)i;
        float4 v0 = __ldg(xp);
        float4 v1 = __ldg(xp + 1);
        __half2 h0 = __floats2half2_rn(v0.x, v0.y);
        __half2 h1 = __floats2half2_rn(v0.z, v0.w);
        __half2 h2 = __floats2half2_rn(v1.x, v1.y);
        __half2 h3 = __floats2half2_rn(v1.z, v1.w);
        uint4 u;
        u.x = *reinterpret_cast<uint32_t*>(&h0);
        u.y = *reinterpret_cast<uint32_t*>(&h1);
        u.z = *reinterpret_cast<uint32_t*>(&h2);
        u.w = *reinterpret_cast<uint32_t*>(&h3);
        reinterpret_cast<uint4*>(g_xh)[i] = u;
    }
}

// ---------------------------------------------------------------------------
// Single-pass decoupled-lookback scan
// ---------------------------------------------------------------------------
__global__ void k_scan_fused() {
    __shared__ int warp_sums[8];
    __shared__ int s_base;
    const int b    = blockIdx.x;
    const int t    = threadIdx.x;
    const int lane = t & 31;
    const int w    = t >> 5;
    const int i    = b * SCAN_B + t;

    int v = (i < N_NODES) ? g_cnt[i] : 0;

    int inc = v;
#pragma unroll
    for (int d = 1; d < 32; d <<= 1) {
        int tt = __shfl_up_sync(0xffffffffu, inc, d);
        if (lane >= d) inc += tt;
    }
    if (lane == 31) warp_sums[w] = inc;
    __syncthreads();
    if (w == 0) {
        int ws = (lane < 8) ? warp_sums[lane] : 0;
#pragma unroll
        for (int d = 1; d < 8; d <<= 1) {
            int tt = __shfl_up_sync(0xffffffffu, ws, d);
            if (lane >= d) ws += tt;
        }
        if (lane < 8) warp_sums[lane] = ws;
    }
    __syncthreads();
    int excl  = inc - v + ((w > 0) ? warp_sums[w - 1] : 0);
    int total = warp_sums[7];

    if (t == 0) {
        if (b == 0) {
            atomicExch(&g_scan_pkt[0], (2ULL << 62) | (unsigned)total);
            s_base = 0;
        } else {
            atomicExch(&g_scan_pkt[b], (1ULL << 62) | (unsigned)total);
            int run = 0;
            int j = b - 1;
            while (true) {
                unsigned long long p;
                while (((p = atomicAdd(&g_scan_pkt[j], 0ULL)) >> 62) == 0) {}
                run += (int)(p & 0xFFFFFFFFULL);
                if ((p >> 62) == 2ULL) break;
                j--;
            }
            atomicExch(&g_scan_pkt[b], (2ULL << 62) | (unsigned)(run + total));
            s_base = run;
        }
    }
    __syncthreads();
    int base = s_base;
    if (i < N_NODES) g_off[i] = base + excl;
    if (i == N_NODES - 1) g_off[N_NODES] = N_EDGES;
}

// ---------------------------------------------------------------------------
// Scatter: atomic-free, position = off[row] + rank
// ---------------------------------------------------------------------------
__global__ __launch_bounds__(256)
void k_scatter(const int*   __restrict__ edge_row,
               const int*   __restrict__ edge_col,
               const float* __restrict__ edge_val) {
    int e = blockIdx.x * blockDim.x + threadIdx.x;
    if (e < N_EDGES) {
        int r = edge_row[e];
        int p = g_off[r] + g_rank[e];
        g_cv[p] = make_int2(edge_col[e], __float_as_int(edge_val[e]));
    }
}

// ---------------------------------------------------------------------------
// GEMM  Y[m,n] = sum_k Xh[m,k]*Wh[n,k]  (fp16 MMA, fp32 acc)
// CTA 128x128, BK=32, 8 warps 4(M) x 2(N), 256 threads, 2 CTAs/SM.
// cp.async double-buffered 2-deep pipeline: zero register prefetch cost.
// ---------------------------------------------------------------------------
#define BM 128
#define BN 128
#define BK 32
#define LDS_K 40
#define KTILES (F_DIM / BK)   // 8

__device__ __forceinline__ void mma_f16(float* c, const uint32_t* a, const uint32_t* b) {
    asm volatile(
        "mma.sync.aligned.m16n8k16.row.col.f32.f16.f16.f32 "
        "{%0,%1,%2,%3}, {%4,%5,%6,%7}, {%8,%9}, {%0,%1,%2,%3};"
        : "+f"(c[0]), "+f"(c[1]), "+f"(c[2]), "+f"(c[3])
        : "r"(a[0]), "r"(a[1]), "r"(a[2]), "r"(a[3]), "r"(b[0]), "r"(b[1]));
}

__global__ __launch_bounds__(256, 2)
void gemm_kernel() {
    __shared__ __half As[2][BM][LDS_K];   // 2 x 10 KB
    __shared__ __half Ws[2][BN][LDS_K];   // 2 x 10 KB

    const int t    = threadIdx.x;
    const int lane = t & 31;
    const int wid  = t >> 5;
    const int wm   = wid & 3;
    const int wn   = wid >> 2;
    const int g    = lane >> 2;
    const int tid4 = lane & 3;

    const int m0 = blockIdx.x * BM;
    const int n0 = blockIdx.y * BN;

    // staging geometry: 2 chunks of 16B (8 halfs) per thread per array
    int rowS[2], c8S[2];
    const __half* xsrc[2];
    const __half* wsrc[2];
    int xsz[2];
    uint32_t adst[2][2], wdst[2][2];      // [buf][i]
#pragma unroll
    for (int i = 0; i < 2; i++) {
        int idx = t + i * 256;            // 0..511
        rowS[i] = idx >> 2;               // 0..127
        c8S[i]  = idx & 3;                // 0..3
        int m   = m0 + rowS[i];
        bool ok = (m < N_NODES);
        xsz[i]  = ok ? 16 : 0;
        xsrc[i] = g_xh + (size_t)(ok ? m : 0) * F_DIM + c8S[i] * 8;
        wsrc[i] = g_wh + (size_t)(n0 + rowS[i]) * F_DIM + c8S[i] * 8;
#pragma unroll
        for (int bu = 0; bu < 2; bu++) {
            adst[bu][i] = (uint32_t)__cvta_generic_to_shared(&As[bu][rowS[i]][c8S[i] * 8]);
            wdst[bu][i] = (uint32_t)__cvta_generic_to_shared(&Ws[bu][rowS[i]][c8S[i] * 8]);
        }
    }

    // prologue: issue tiles 0 and 1
#pragma unroll
    for (int kt = 0; kt < 2; kt++) {
        int koff = kt * BK;
#pragma unroll
        for (int i = 0; i < 2; i++) {
            cp_async16(adst[kt][i], xsrc[i] + koff, xsz[i]);
            cp_async16(wdst[kt][i], wsrc[i] + koff, 16);
        }
        cp_commit();
    }

    float acc[2][8][4];
#pragma unroll
    for (int i = 0; i < 2; i++)
#pragma unroll
        for (int j = 0; j < 8; j++)
#pragma unroll
            for (int k = 0; k < 4; k++) acc[i][j][k] = 0.f;

#pragma unroll
    for (int kt = 0; kt < KTILES; kt++) {
        const int buf = kt & 1;
        cp_wait<1>();                      // tile kt's group complete
        __syncthreads();

        // compute from smem[buf]
#pragma unroll
        for (int ks = 0; ks < 2; ks++) {
            int kb = ks * 16;
            uint32_t a[2][4];
#pragma unroll
            for (int mi = 0; mi < 2; mi++) {
                int r = wm * 32 + mi * 16;
                a[mi][0] = *reinterpret_cast<const uint32_t*>(&As[buf][r + g    ][kb + 2 * tid4]);
                a[mi][1] = *reinterpret_cast<const uint32_t*>(&As[buf][r + g + 8][kb + 2 * tid4]);
                a[mi][2] = *reinterpret_cast<const uint32_t*>(&As[buf][r + g    ][kb + 2 * tid4 + 8]);
                a[mi][3] = *reinterpret_cast<const uint32_t*>(&As[buf][r + g + 8][kb + 2 * tid4 + 8]);
            }
            uint32_t b[8][2];
#pragma unroll
            for (int ni = 0; ni < 8; ni++) {
                int n = wn * 64 + ni * 8 + g;
                b[ni][0] = *reinterpret_cast<const uint32_t*>(&Ws[buf][n][kb + 2 * tid4]);
                b[ni][1] = *reinterpret_cast<const uint32_t*>(&Ws[buf][n][kb + 2 * tid4 + 8]);
            }
#pragma unroll
            for (int mi = 0; mi < 2; mi++)
#pragma unroll
                for (int ni = 0; ni < 8; ni++)
                    mma_f16(acc[mi][ni], a[mi], b[ni]);
        }
        __syncthreads();                   // all warps done with smem[buf]

        // issue tile kt+2 into smem[buf]
        if (kt + 2 < KTILES) {
            int koff = (kt + 2) * BK;
#pragma unroll
            for (int i = 0; i < 2; i++) {
                cp_async16(adst[buf][i], xsrc[i] + koff, xsz[i]);
                cp_async16(wdst[buf][i], wsrc[i] + koff, 16);
            }
            cp_commit();
        } else {
            cp_commit();                   // keep group count in step for cp_wait<1>
        }
    }

    // store Y as fp16
#pragma unroll
    for (int mi = 0; mi < 2; mi++) {
        int r_base = m0 + wm * 32 + mi * 16;
#pragma unroll
        for (int ni = 0; ni < 8; ni++) {
            int col = n0 + wn * 64 + ni * 8 + 2 * tid4;
            int r0 = r_base + g;
            int r1 = r_base + g + 8;
            if (r0 < N_NODES) {
                __half2 h = __floats2half2_rn(acc[mi][ni][0], acc[mi][ni][1]);
                *reinterpret_cast<__half2*>(g_yh + (size_t)r0 * F_DIM + col) = h;
            }
            if (r1 < N_NODES) {
                __half2 h = __floats2half2_rn(acc[mi][ni][2], acc[mi][ni][3]);
                *reinterpret_cast<__half2*>(g_yh + (size_t)r1 * F_DIM + col) = h;
            }
        }
    }
}

// ---------------------------------------------------------------------------
// Gather: out[r] = sum_e val_e * Y[col_e] + b.  One warp per row. FFMA2.
// ---------------------------------------------------------------------------
__device__ __forceinline__ void fma8_x2(unsigned long long* acc, uint4 u,
                                        unsigned long long v2) {
    const __half2* h = reinterpret_cast<const __half2*>(&u);
#pragma unroll
    for (int q = 0; q < 4; q++) {
        float2 f = __half22float2(h[q]);
        unsigned long long fu;
        asm("mov.b64 %0, {%1, %2};" : "=l"(fu) : "f"(f.x), "f"(f.y));
        asm("fma.rn.f32x2 %0, %1, %2, %0;" : "+l"(acc[q]) : "l"(fu), "l"(v2));
    }
}

__global__ __launch_bounds__(256, 6)
void k_gather(const float* __restrict__ bias, float* __restrict__ out) {
    int r    = (blockIdx.x * blockDim.x + threadIdx.x) >> 5;
    int lane = threadIdx.x & 31;
    if (r >= N_NODES) return;

    unsigned long long acc[4];
#pragma unroll
    for (int q = 0; q < 4; q++) acc[q] = 0ULL;

    int start = g_off[r];
    int end   = g_off[r + 1];

    for (int base = start; base < end; base += 32) {
        int n = min(32, end - base);
        int   col = 0;
        float val = 0.f;
        if (lane < n) {
            int2 cv = __ldg(&g_cv[base + lane]);
            col = cv.x;
            val = __int_as_float(cv.y);
        }
        int j = 0;
        for (; j + 4 <= n; j += 4) {
            int   c0 = __shfl_sync(0xffffffffu, col, j);
            int   c1 = __shfl_sync(0xffffffffu, col, j + 1);
            int   c2 = __shfl_sync(0xffffffffu, col, j + 2);
            int   c3 = __shfl_sync(0xffffffffu, col, j + 3);
            float v0 = __shfl_sync(0xffffffffu, val, j);
            float v1 = __shfl_sync(0xffffffffu, val, j + 1);
            float v2 = __shfl_sync(0xffffffffu, val, j + 2);
            float v3 = __shfl_sync(0xffffffffu, val, j + 3);
            uint4 u0 = __ldg(reinterpret_cast<const uint4*>(g_yh + (size_t)c0 * F_DIM) + lane);
            uint4 u1 = __ldg(reinterpret_cast<const uint4*>(g_yh + (size_t)c1 * F_DIM) + lane);
            uint4 u2 = __ldg(reinterpret_cast<const uint4*>(g_yh + (size_t)c2 * F_DIM) + lane);
            uint4 u3 = __ldg(reinterpret_cast<const uint4*>(g_yh + (size_t)c3 * F_DIM) + lane);
            unsigned long long p0, p1, p2, p3;
            asm("mov.b64 %0, {%1, %1};" : "=l"(p0) : "f"(v0));
            asm("mov.b64 %0, {%1, %1};" : "=l"(p1) : "f"(v1));
            asm("mov.b64 %0, {%1, %1};" : "=l"(p2) : "f"(v2));
            asm("mov.b64 %0, {%1, %1};" : "=l"(p3) : "f"(v3));
            fma8_x2(acc, u0, p0);
            fma8_x2(acc, u1, p1);
            fma8_x2(acc, u2, p2);
            fma8_x2(acc, u3, p3);
        }
        for (; j < n; j++) {
            int   c = __shfl_sync(0xffffffffu, col, j);
            float v = __shfl_sync(0xffffffffu, val, j);
            uint4 u = __ldg(reinterpret_cast<const uint4*>(g_yh + (size_t)c * F_DIM) + lane);
            unsigned long long p;
            asm("mov.b64 %0, {%1, %1};" : "=l"(p) : "f"(v));
            fma8_x2(acc, u, p);
        }
    }

    float a[8];
#pragma unroll
    for (int q = 0; q < 4; q++) {
        float lo, hi;
        asm("mov.b64 {%0, %1}, %2;" : "=f"(lo), "=f"(hi) : "l"(acc[q]));
        a[2 * q]     = lo;
        a[2 * q + 1] = hi;
    }
    const float4* bp = reinterpret_cast<const float4*>(bias + lane * 8);
    float4 b0 = __ldg(bp);
    float4 b1 = __ldg(bp + 1);
    float4 o0 = make_float4(a[0] + b0.x, a[1] + b0.y, a[2] + b0.z, a[3] + b0.w);
    float4 o1 = make_float4(a[4] + b1.x, a[5] + b1.y, a[6] + b1.z, a[7] + b1.w);
    float4* orow = reinterpret_cast<float4*>(out + (size_t)r * F_DIM + lane * 8);
    orow[0] = o0;
    orow[1] = o1;
}

// ---------------------------------------------------------------------------
// Launch
// ---------------------------------------------------------------------------
extern "C" void kernel_launch(void* const* d_in, const int* in_sizes, int n_in,
                              void* d_out, int out_size) {
    const float* x        = (const float*)d_in[0];
    const int*   edge_row = (const int*)  d_in[1];
    const int*   edge_col = (const int*)  d_in[2];
    const float* edge_val = (const float*)d_in[3];
    const float* W        = (const float*)d_in[4];
    const float* b        = (const float*)d_in[5];
    float*       out      = (float*)d_out;

    void* cnt_ptr = nullptr;
    cudaGetSymbolAddress(&cnt_ptr, g_cnt);
    cudaMemsetAsync(cnt_ptr, 0, N_NODES * sizeof(int));
    void* pkt_ptr = nullptr;
    cudaGetSymbolAddress(&pkt_ptr, g_scan_pkt);
    cudaMemsetAsync(pkt_ptr, 0, SCAN_NB * sizeof(unsigned long long));

    // A: hist (+rank) | prep_w | prep_x
    k_fused_a<<<F1_BLOCKS, 256>>>(edge_row, W, x);
    // B: scan
    k_scan_fused<<<SCAN_NB, SCAN_B>>>();
    // C: scatter (atomic-free)
    k_scatter<<<(N_EDGES + 255) / 256, 256>>>(edge_row, edge_col, edge_val);
    // D: GEMM (cp.async pipelined, fp16 in/out)
    dim3 grid(PAD_M / BM, F_DIM / BN);   // 391 x 2
    gemm_kernel<<<grid, 256>>>();
    // E: gather
    k_gather<<<(N_NODES * 32 + 255) / 256, 256>>>(b, out);
}

// round 13
// speedup vs baseline: 1.3161x; 1.1381x over previous
#include <cuda_runtime.h>
#include <cuda_fp16.h>
#include <cstdint>

#define N_NODES   50000
#define F_DIM     256
#define N_EDGES   800000
#define PAD_M     50048          // 391 * 128

#define SCAN_B    256
#define SCAN_NB   ((N_NODES + SCAN_B - 1) / SCAN_B)   // 196

// prep roles: prep_w | prep_x
#define PREPW_B   64
#define PREPX_B   6250
#define PREP_BLOCKS (PREPW_B + PREPX_B)

// Scratch (__device__ globals; no allocation allowed)
__device__ __half g_yh[(size_t)N_NODES * F_DIM];  // Y = X @ W^T, fp16
__device__ __half g_xh[(size_t)N_NODES * F_DIM];  // X in fp16
__device__ __half g_wh[F_DIM * F_DIM];            // W in fp16
__device__ int    g_cnt[N_NODES];
__device__ int    g_off[N_NODES + 1];
__device__ int    g_rank[N_EDGES];                // edge rank within its row
__device__ unsigned long long g_scan_pkt[SCAN_NB];
__device__ int2   g_cv[N_EDGES];                  // packed (col, val-bits)

// ---------------------------------------------------------------------------
// cp.async helpers
// ---------------------------------------------------------------------------
__device__ __forceinline__ void cp_async16(uint32_t smem_addr, const void* gptr,
                                           int src_size) {
    asm volatile("cp.async.cg.shared.global [%0], [%1], 16, %2;"
                 :: "r"(smem_addr), "l"(gptr), "r"(src_size));
}
__device__ __forceinline__ void cp_commit() { asm volatile("cp.async.commit_group;"); }
template <int N>
__device__ __forceinline__ void cp_wait() {
    asm volatile("cp.async.wait_group %0;" :: "n"(N));
}

// ---------------------------------------------------------------------------
// Stream A: hist (stores per-edge rank)
// ---------------------------------------------------------------------------
__global__ __launch_bounds__(256)
void k_hist(const int* __restrict__ edge_row) {
    int e = blockIdx.x * blockDim.x + threadIdx.x;
    if (e < N_EDGES) {
        int r = edge_row[e];
        g_rank[e] = atomicAdd(&g_cnt[r], 1);
    }
}

// ---------------------------------------------------------------------------
// Stream B: prep_w | prep_x
// ---------------------------------------------------------------------------
__global__ __launch_bounds__(256)
void k_prep(const float* __restrict__ W, const float* __restrict__ X) {
    int bid = blockIdx.x;
    int tid = threadIdx.x;
    if (bid < PREPW_B) {
        int i = bid * 256 + tid;                   // float4 index, 16384 total
        float4 v = reinterpret_cast<const float4*>(W)[i];
        __half2 h0 = __floats2half2_rn(v.x, v.y);
        __half2 h1 = __floats2half2_rn(v.z, v.w);
        reinterpret_cast<__half2*>(g_wh)[2 * i]     = h0;
        reinterpret_cast<__half2*>(g_wh)[2 * i + 1] = h1;
    } else {
        int i = (bid - PREPW_B) * 256 + tid;       // 8-half chunk
        const float4* xp = reinterpret_cast<const float4*>(X) + 2 * (size_t)i;
        float4 v0 = __ldg(xp);
        float4 v1 = __ldg(xp + 1);
        __half2 h0 = __floats2half2_rn(v0.x, v0.y);
        __half2 h1 = __floats2half2_rn(v0.z, v0.w);
        __half2 h2 = __floats2half2_rn(v1.x, v1.y);
        __half2 h3 = __floats2half2_rn(v1.z, v1.w);
        uint4 u;
        u.x = *reinterpret_cast<uint32_t*>(&h0);
        u.y = *reinterpret_cast<uint32_t*>(&h1);
        u.z = *reinterpret_cast<uint32_t*>(&h2);
        u.w = *reinterpret_cast<uint32_t*>(&h3);
        reinterpret_cast<uint4*>(g_xh)[i] = u;
    }
}

// ---------------------------------------------------------------------------
// Single-pass decoupled-lookback scan
// ---------------------------------------------------------------------------
__global__ void k_scan_fused() {
    __shared__ int warp_sums[8];
    __shared__ int s_base;
    const int b    = blockIdx.x;
    const int t    = threadIdx.x;
    const int lane = t & 31;
    const int w    = t >> 5;
    const int i    = b * SCAN_B + t;

    int v = (i < N_NODES) ? g_cnt[i] : 0;

    int inc = v;
#pragma unroll
    for (int d = 1; d < 32; d <<= 1) {
        int tt = __shfl_up_sync(0xffffffffu, inc, d);
        if (lane >= d) inc += tt;
    }
    if (lane == 31) warp_sums[w] = inc;
    __syncthreads();
    if (w == 0) {
        int ws = (lane < 8) ? warp_sums[lane] : 0;
#pragma unroll
        for (int d = 1; d < 8; d <<= 1) {
            int tt = __shfl_up_sync(0xffffffffu, ws, d);
            if (lane >= d) ws += tt;
        }
        if (lane < 8) warp_sums[lane] = ws;
    }
    __syncthreads();
    int excl  = inc - v + ((w > 0) ? warp_sums[w - 1] : 0);
    int total = warp_sums[7];

    if (t == 0) {
        if (b == 0) {
            atomicExch(&g_scan_pkt[0], (2ULL << 62) | (unsigned)total);
            s_base = 0;
        } else {
            atomicExch(&g_scan_pkt[b], (1ULL << 62) | (unsigned)total);
            int run = 0;
            int j = b - 1;
            while (true) {
                unsigned long long p;
                while (((p = atomicAdd(&g_scan_pkt[j], 0ULL)) >> 62) == 0) {}
                run += (int)(p & 0xFFFFFFFFULL);
                if ((p >> 62) == 2ULL) break;
                j--;
            }
            atomicExch(&g_scan_pkt[b], (2ULL << 62) | (unsigned)(run + total));
            s_base = run;
        }
    }
    __syncthreads();
    int base = s_base;
    if (i < N_NODES) g_off[i] = base + excl;
    if (i == N_NODES - 1) g_off[N_NODES] = N_EDGES;
}

// ---------------------------------------------------------------------------
// Scatter: atomic-free, position = off[row] + rank
// ---------------------------------------------------------------------------
__global__ __launch_bounds__(256)
void k_scatter(const int*   __restrict__ edge_row,
               const int*   __restrict__ edge_col,
               const float* __restrict__ edge_val) {
    int e = blockIdx.x * blockDim.x + threadIdx.x;
    if (e < N_EDGES) {
        int r = edge_row[e];
        int p = g_off[r] + g_rank[e];
        g_cv[p] = make_int2(edge_col[e], __float_as_int(edge_val[e]));
    }
}

// ---------------------------------------------------------------------------
// GEMM  Y[m,n] = sum_k Xh[m,k]*Wh[n,k]  (fp16 MMA, fp32 acc)
// CTA 128x128, BK=32, 8 warps 4(M) x 2(N), 256 threads, 2 CTAs/SM.
// cp.async double-buffered 2-deep pipeline (R11-proven, 32.9us).
// ---------------------------------------------------------------------------
#define BM 128
#define BN 128
#define BK 32
#define LDS_K 40
#define KTILES (F_DIM / BK)   // 8

__device__ __forceinline__ void mma_f16(float* c, const uint32_t* a, const uint32_t* b) {
    asm volatile(
        "mma.sync.aligned.m16n8k16.row.col.f32.f16.f16.f32 "
        "{%0,%1,%2,%3}, {%4,%5,%6,%7}, {%8,%9}, {%0,%1,%2,%3};"
        : "+f"(c[0]), "+f"(c[1]), "+f"(c[2]), "+f"(c[3])
        : "r"(a[0]), "r"(a[1]), "r"(a[2]), "r"(a[3]), "r"(b[0]), "r"(b[1]));
}

__global__ __launch_bounds__(256, 2)
void gemm_kernel() {
    __shared__ __half As[2][BM][LDS_K];
    __shared__ __half Ws[2][BN][LDS_K];

    const int t    = threadIdx.x;
    const int lane = t & 31;
    const int wid  = t >> 5;
    const int wm   = wid & 3;
    const int wn   = wid >> 2;
    const int g    = lane >> 2;
    const int tid4 = lane & 3;

    const int m0 = blockIdx.x * BM;
    const int n0 = blockIdx.y * BN;

    int rowS[2], c8S[2];
    const __half* xsrc[2];
    const __half* wsrc[2];
    int xsz[2];
    uint32_t adst[2][2], wdst[2][2];
#pragma unroll
    for (int i = 0; i < 2; i++) {
        int idx = t + i * 256;
        rowS[i] = idx >> 2;
        c8S[i]  = idx & 3;
        int m   = m0 + rowS[i];
        bool ok = (m < N_NODES);
        xsz[i]  = ok ? 16 : 0;
        xsrc[i] = g_xh + (size_t)(ok ? m : 0) * F_DIM + c8S[i] * 8;
        wsrc[i] = g_wh + (size_t)(n0 + rowS[i]) * F_DIM + c8S[i] * 8;
#pragma unroll
        for (int bu = 0; bu < 2; bu++) {
            adst[bu][i] = (uint32_t)__cvta_generic_to_shared(&As[bu][rowS[i]][c8S[i] * 8]);
            wdst[bu][i] = (uint32_t)__cvta_generic_to_shared(&Ws[bu][rowS[i]][c8S[i] * 8]);
        }
    }

#pragma unroll
    for (int kt = 0; kt < 2; kt++) {
        int koff = kt * BK;
#pragma unroll
        for (int i = 0; i < 2; i++) {
            cp_async16(adst[kt][i], xsrc[i] + koff, xsz[i]);
            cp_async16(wdst[kt][i], wsrc[i] + koff, 16);
        }
        cp_commit();
    }

    float acc[2][8][4];
#pragma unroll
    for (int i = 0; i < 2; i++)
#pragma unroll
        for (int j = 0; j < 8; j++)
#pragma unroll
            for (int k = 0; k < 4; k++) acc[i][j][k] = 0.f;

#pragma unroll
    for (int kt = 0; kt < KTILES; kt++) {
        const int buf = kt & 1;
        cp_wait<1>();
        __syncthreads();

#pragma unroll
        for (int ks = 0; ks < 2; ks++) {
            int kb = ks * 16;
            uint32_t a[2][4];
#pragma unroll
            for (int mi = 0; mi < 2; mi++) {
                int r = wm * 32 + mi * 16;
                a[mi][0] = *reinterpret_cast<const uint32_t*>(&As[buf][r + g    ][kb + 2 * tid4]);
                a[mi][1] = *reinterpret_cast<const uint32_t*>(&As[buf][r + g + 8][kb + 2 * tid4]);
                a[mi][2] = *reinterpret_cast<const uint32_t*>(&As[buf][r + g    ][kb + 2 * tid4 + 8]);
                a[mi][3] = *reinterpret_cast<const uint32_t*>(&As[buf][r + g + 8][kb + 2 * tid4 + 8]);
            }
            uint32_t b[8][2];
#pragma unroll
            for (int ni = 0; ni < 8; ni++) {
                int n = wn * 64 + ni * 8 + g;
                b[ni][0] = *reinterpret_cast<const uint32_t*>(&Ws[buf][n][kb + 2 * tid4]);
                b[ni][1] = *reinterpret_cast<const uint32_t*>(&Ws[buf][n][kb + 2 * tid4 + 8]);
            }
#pragma unroll
            for (int mi = 0; mi < 2; mi++)
#pragma unroll
                for (int ni = 0; ni < 8; ni++)
                    mma_f16(acc[mi][ni], a[mi], b[ni]);
        }
        __syncthreads();

        if (kt + 2 < KTILES) {
            int koff = (kt + 2) * BK;
#pragma unroll
            for (int i = 0; i < 2; i++) {
                cp_async16(adst[buf][i], xsrc[i] + koff, xsz[i]);
                cp_async16(wdst[buf][i], wsrc[i] + koff, 16);
            }
            cp_commit();
        } else {
            cp_commit();
        }
    }

#pragma unroll
    for (int mi = 0; mi < 2; mi++) {
        int r_base = m0 + wm * 32 + mi * 16;
#pragma unroll
        for (int ni = 0; ni < 8; ni++) {
            int col = n0 + wn * 64 + ni * 8 + 2 * tid4;
            int r0 = r_base + g;
            int r1 = r_base + g + 8;
            if (r0 < N_NODES) {
                __half2 h = __floats2half2_rn(acc[mi][ni][0], acc[mi][ni][1]);
                *reinterpret_cast<__half2*>(g_yh + (size_t)r0 * F_DIM + col) = h;
            }
            if (r1 < N_NODES) {
                __half2 h = __floats2half2_rn(acc[mi][ni][2], acc[mi][ni][3]);
                *reinterpret_cast<__half2*>(g_yh + (size_t)r1 * F_DIM + col) = h;
            }
        }
    }
}

// ---------------------------------------------------------------------------
// Gather: out[r] = sum_e val_e * Y[col_e] + b.  One warp per row. FFMA2.
// ---------------------------------------------------------------------------
__device__ __forceinline__ void fma8_x2(unsigned long long* acc, uint4 u,
                                        unsigned long long v2) {
    const __half2* h = reinterpret_cast<const __half2*>(&u);
#pragma unroll
    for (int q = 0; q < 4; q++) {
        float2 f = __half22float2(h[q]);
        unsigned long long fu;
        asm("mov.b64 %0, {%1, %2};" : "=l"(fu) : "f"(f.x), "f"(f.y));
        asm("fma.rn.f32x2 %0, %1, %2, %0;" : "+l"(acc[q]) : "l"(fu), "l"(v2));
    }
}

__global__ __launch_bounds__(256, 6)
void k_gather(const float* __restrict__ bias, float* __restrict__ out) {
    int r    = (blockIdx.x * blockDim.x + threadIdx.x) >> 5;
    int lane = threadIdx.x & 31;
    if (r >= N_NODES) return;

    unsigned long long acc[4];
#pragma unroll
    for (int q = 0; q < 4; q++) acc[q] = 0ULL;

    int start = g_off[r];
    int end   = g_off[r + 1];

    for (int base = start; base < end; base += 32) {
        int n = min(32, end - base);
        int   col = 0;
        float val = 0.f;
        if (lane < n) {
            int2 cv = __ldg(&g_cv[base + lane]);
            col = cv.x;
            val = __int_as_float(cv.y);
        }
        int j = 0;
        for (; j + 4 <= n; j += 4) {
            int   c0 = __shfl_sync(0xffffffffu, col, j);
            int   c1 = __shfl_sync(0xffffffffu, col, j + 1);
            int   c2 = __shfl_sync(0xffffffffu, col, j + 2);
            int   c3 = __shfl_sync(0xffffffffu, col, j + 3);
            float v0 = __shfl_sync(0xffffffffu, val, j);
            float v1 = __shfl_sync(0xffffffffu, val, j + 1);
            float v2 = __shfl_sync(0xffffffffu, val, j + 2);
            float v3 = __shfl_sync(0xffffffffu, val, j + 3);
            uint4 u0 = __ldg(reinterpret_cast<const uint4*>(g_yh + (size_t)c0 * F_DIM) + lane);
            uint4 u1 = __ldg(reinterpret_cast<const uint4*>(g_yh + (size_t)c1 * F_DIM) + lane);
            uint4 u2 = __ldg(reinterpret_cast<const uint4*>(g_yh + (size_t)c2 * F_DIM) + lane);
            uint4 u3 = __ldg(reinterpret_cast<const uint4*>(g_yh + (size_t)c3 * F_DIM) + lane);
            unsigned long long p0, p1, p2, p3;
            asm("mov.b64 %0, {%1, %1};" : "=l"(p0) : "f"(v0));
            asm("mov.b64 %0, {%1, %1};" : "=l"(p1) : "f"(v1));
            asm("mov.b64 %0, {%1, %1};" : "=l"(p2) : "f"(v2));
            asm("mov.b64 %0, {%1, %1};" : "=l"(p3) : "f"(v3));
            fma8_x2(acc, u0, p0);
            fma8_x2(acc, u1, p1);
            fma8_x2(acc, u2, p2);
            fma8_x2(acc, u3, p3);
        }
        for (; j < n; j++) {
            int   c = __shfl_sync(0xffffffffu, col, j);
            float v = __shfl_sync(0xffffffffu, val, j);
            uint4 u = __ldg(reinterpret_cast<const uint4*>(g_yh + (size_t)c * F_DIM) + lane);
            unsigned long long p;
            asm("mov.b64 %0, {%1, %1};" : "=l"(p) : "f"(v));
            fma8_x2(acc, u, p);
        }
    }

    float a[8];
#pragma unroll
    for (int q = 0; q < 4; q++) {
        float lo, hi;
        asm("mov.b64 {%0, %1}, %2;" : "=f"(lo), "=f"(hi) : "l"(acc[q]));
        a[2 * q]     = lo;
        a[2 * q + 1] = hi;
    }
    const float4* bp = reinterpret_cast<const float4*>(bias + lane * 8);
    float4 b0 = __ldg(bp);
    float4 b1 = __ldg(bp + 1);
    float4 o0 = make_float4(a[0] + b0.x, a[1] + b0.y, a[2] + b0.z, a[3] + b0.w);
    float4 o1 = make_float4(a[4] + b1.x, a[5] + b1.y, a[6] + b1.z, a[7] + b1.w);
    float4* orow = reinterpret_cast<float4*>(out + (size_t)r * F_DIM + lane * 8);
    orow[0] = o0;
    orow[1] = o1;
}

// ---------------------------------------------------------------------------
// Launch: fork/join two independent chains (capture-legal event pattern)
//   chain A (default stream): memsets -> hist -> scan -> scatter
//   chain B (s2):             prep(W,X) -> gemm
//   join -> gather
// ---------------------------------------------------------------------------
extern "C" void kernel_launch(void* const* d_in, const int* in_sizes, int n_in,
                              void* d_out, int out_size) {
    const float* x        = (const float*)d_in[0];
    const int*   edge_row = (const int*)  d_in[1];
    const int*   edge_col = (const int*)  d_in[2];
    const float* edge_val = (const float*)d_in[3];
    const float* W        = (const float*)d_in[4];
    const float* b        = (const float*)d_in[5];
    float*       out      = (float*)d_out;

    // lazily created host-side resources (no device memory involved;
    // identical captured work on every call)
    static cudaStream_t s2 = nullptr;
    static cudaEvent_t  ev_fork = nullptr, ev_join = nullptr;
    if (s2 == nullptr) {
        cudaStreamCreateWithFlags(&s2, cudaStreamNonBlocking);
        cudaEventCreateWithFlags(&ev_fork, cudaEventDisableTiming);
        cudaEventCreateWithFlags(&ev_join, cudaEventDisableTiming);
    }

    // ---- fork ----
    cudaEventRecord(ev_fork, 0);
    cudaStreamWaitEvent(s2, ev_fork, 0);

    // ---- chain A: CSR build (default stream) ----
    void* cnt_ptr = nullptr;
    cudaGetSymbolAddress(&cnt_ptr, g_cnt);
    cudaMemsetAsync(cnt_ptr, 0, N_NODES * sizeof(int));
    void* pkt_ptr = nullptr;
    cudaGetSymbolAddress(&pkt_ptr, g_scan_pkt);
    cudaMemsetAsync(pkt_ptr, 0, SCAN_NB * sizeof(unsigned long long));
    k_hist<<<(N_EDGES + 255) / 256, 256>>>(edge_row);
    k_scan_fused<<<SCAN_NB, SCAN_B>>>();
    k_scatter<<<(N_EDGES + 255) / 256, 256>>>(edge_row, edge_col, edge_val);

    // ---- chain B: prep + GEMM (s2) ----
    k_prep<<<PREP_BLOCKS, 256, 0, s2>>>(W, x);
    {
        dim3 grid(PAD_M / BM, F_DIM / BN);   // 391 x 2
        gemm_kernel<<<grid, 256, 0, s2>>>();
    }

    // ---- join ----
    cudaEventRecord(ev_join, s2);
    cudaStreamWaitEvent(0, ev_join, 0);

    // ---- gather (needs scatter + gemm) ----
    k_gather<<<(N_NODES * 32 + 255) / 256, 256>>>(b, out);
}